// round 12
// baseline (speedup 1.0000x reference)
#include <cuda_runtime.h>
#include <cuda_fp16.h>
#include <math.h>

#define NMAX    50000
#define EMAX    1700000   // E + N upper bound
#define INCH    7
#define HID     64
#define HEADS   4
#define F1      (HEADS*HID)   // 256
#define OUTCH   6
#define NB_MAX  256       // ceil(NMAX/256) = 196 <= 256

// Scratch (static __device__ — allocation is forbidden)
__device__ __align__(16) __half g_h1h[NMAX * F1]; // layer-1 features, fp16
__device__ __align__(16) float  g_al1[NMAX * 8];  // [al_src1[4], al_dst1[4]] (fp32)
__device__ __align__(16) float  g_den1[NMAX * 4]; // per-head denominators (atomic)
__device__ __align__(16) float  g_h2 [NMAX * 8];  // [h2[6], al_src2, al_dst2]
__device__ __align__(16) unsigned short g_wqh[EMAX * 4]; // per-edge weights, fp16 x 4 heads
__device__ int g_cnt   [NMAX];
__device__ int g_offs  [NMAX + 1];
__device__ int g_cursor[NMAX];
__device__ int g_sorted[EMAX];                    // src ids grouped by dst
__device__ int g_src32 [EMAX];
__device__ int g_dst32 [EMAX];
__device__ int g_pub   [NB_MAX];                  // decoupled-lookback publish slots

__device__ __forceinline__ float lrelu(float v) { return v > 0.f ? v : 0.2f * v; }

__device__ __forceinline__ void red4(float* p, float a, float b, float c, float d) {
    unsigned long long ga = __cvta_generic_to_global(p);
    asm volatile("red.global.add.v4.f32 [%0], {%1,%2,%3,%4};"
                 :: "l"(ga), "f"(a), "f"(b), "f"(c), "f"(d) : "memory");
}

// accumulate one fp16 row (uint4 = 4 x half2) into 4 half2 accumulators
__device__ __forceinline__ void acc_row16(__half2* a, uint4 r, __half2 wh) {
    a[0] = __hfma2(wh, *(__half2*)&r.x, a[0]);
    a[1] = __hfma2(wh, *(__half2*)&r.y, a[1]);
    a[2] = __hfma2(wh, *(__half2*)&r.z, a[2]);
    a[3] = __hfma2(wh, *(__half2*)&r.w, a[3]);
}

// ---------------- FUSED: node transform 1 | edge histogram ----------------
__global__ void __launch_bounds__(256) k_node1_hist(
    const float* __restrict__ x, const float* __restrict__ W1,
    const float* __restrict__ a_src1, const float* __restrict__ a_dst1,
    const void* __restrict__ ei, int E, int N, int NBn)
{
    int tid = threadIdx.x;
    if ((int)blockIdx.x >= NBn) {
        // ---- histogram part ----
        int hb = blockIdx.x - NBn;
        if (hb == 0 && tid < NB_MAX) g_pub[tid] = 0;

        int ok = 1;
        int m = (E * 2 < 64) ? E * 2 : 64;
        if (tid < m) {
            long long v = ((const long long*)ei)[tid];
            ok = (v >= 0 && v < N);
        }
        int is64 = __syncthreads_and(ok);

        int e = hb * 256 + tid;
        int total = E + N;
        if (e >= total) return;
        int dst;
        if (e < E) {
            int src;
            if (is64) {
                const long long* p = (const long long*)ei;
                src = (int)p[e]; dst = (int)p[E + e];
            } else {
                const int* p = (const int*)ei;
                src = p[e]; dst = p[E + e];
            }
            g_src32[e] = src;
            g_dst32[e] = dst;
        } else {
            dst = e - E;
        }
        atomicAdd(&g_cnt[dst], 1);
        return;
    }

    // ---- node transform part ----
    __shared__ float W1s[INCH * F1];
    __shared__ float as1[F1], ad1[F1];
    for (int i = tid; i < INCH * F1; i += 256) W1s[i] = W1[i];
    as1[tid] = a_src1[tid];
    ad1[tid] = a_dst1[tid];
    __syncthreads();

    int n = blockIdx.x * 8 + (tid >> 5);
    if (n >= N) return;
    int lane = tid & 31;
    int c0 = lane * 8;
    int head = lane >> 3;

    float xv = (lane < INCH) ? x[n * INCH + lane] : 0.f;
    float h[8];
#pragma unroll
    for (int j = 0; j < 8; j++) h[j] = 0.f;
#pragma unroll
    for (int i = 0; i < INCH; i++) {
        float xi = __shfl_sync(0xffffffffu, xv, i);
#pragma unroll
        for (int j = 0; j < 8; j++) h[j] = fmaf(xi, W1s[i * F1 + c0 + j], h[j]);
    }
    // store fp16 features (8 halfs = 16B per lane)
    union { __half2 q[4]; uint4 u; } pk;
#pragma unroll
    for (int j = 0; j < 4; j++) pk.q[j] = __floats2half2_rn(h[2 * j], h[2 * j + 1]);
    *(uint4*)(g_h1h + (size_t)n * F1 + c0) = pk.u;

    float ps = 0.f, pd = 0.f;
#pragma unroll
    for (int j = 0; j < 8; j++) {
        ps = fmaf(h[j], as1[c0 + j], ps);
        pd = fmaf(h[j], ad1[c0 + j], pd);
    }
#pragma unroll
    for (int s = 4; s >= 1; s >>= 1) {
        ps += __shfl_down_sync(0xffffffffu, ps, s, 8);
        pd += __shfl_down_sync(0xffffffffu, pd, s, 8);
    }
    if ((lane & 7) == 0) {
        g_al1[n * 8 + head]     = ps;
        g_al1[n * 8 + 4 + head] = pd;
    }
}

// ---------------- CSR scan: single kernel, decoupled lookback ----------------
__global__ void __launch_bounds__(256) k_scan(int N, int NB) {
    int b = blockIdx.x, t = threadIdx.x;
    int i = b * 256 + t;
    int c = (i < N) ? g_cnt[i] : 0;
    int v = c;
#pragma unroll
    for (int s = 1; s < 32; s <<= 1) {
        int u = __shfl_up_sync(0xffffffffu, v, s);
        if ((t & 31) >= s) v += u;
    }
    __shared__ int wsum[8];
    __shared__ int s_agg, s_base;
    if ((t & 31) == 31) wsum[t >> 5] = v;
    __syncthreads();
    if (t == 0) {
        int run = 0;
#pragma unroll
        for (int w = 0; w < 8; w++) { int x = wsum[w]; wsum[w] = run; run += x; }
        s_agg = run;
        atomicExch(&g_pub[b], run + 1);
    }
    __syncthreads();
    int loc = v - c + wsum[t >> 5];

    int pred = 0;
    if (t < b) {
        int x;
        while ((x = atomicAdd(&g_pub[t], 0)) == 0) {}
        pred = x - 1;
    }
#pragma unroll
    for (int s = 16; s >= 1; s >>= 1) pred += __shfl_down_sync(0xffffffffu, pred, s);
    __shared__ int psum[8];
    if ((t & 31) == 0) psum[t >> 5] = pred;
    __syncthreads();
    if (t == 0) {
        int base = 0;
#pragma unroll
        for (int w = 0; w < 8; w++) base += psum[w];
        s_base = base;
    }
    __syncthreads();
    int o = loc + s_base;
    if (i < N) { g_offs[i] = o; g_cursor[i] = o; }
    if (b == NB - 1 && t == 0) g_offs[N] = s_base + s_agg;
}

// ---------------- CSR scatter + weight computation (fp16) + den accumulation ----------------
__global__ void k_scatter(int E, int N) {
    int e = blockIdx.x * blockDim.x + threadIdx.x;
    int total = E + N;
    if (e >= total) return;
    int src, dst;
    if (e < E) { src = g_src32[e]; dst = g_dst32[e]; }
    else       { src = dst = e - E; }
    int pos = atomicAdd(&g_cursor[dst], 1);
    g_sorted[pos] = src;

    float4 s4 = *(const float4*)(g_al1 + (size_t)src * 8);
    float4 d4 = *(const float4*)(g_al1 + (size_t)dst * 8 + 4);
    __half h0 = __float2half_rn(__expf(lrelu(s4.x + d4.x)));
    __half h1 = __float2half_rn(__expf(lrelu(s4.y + d4.y)));
    __half h2v = __float2half_rn(__expf(lrelu(s4.z + d4.z)));
    __half h3 = __float2half_rn(__expf(lrelu(s4.w + d4.w)));
    ushort4 pk;
    pk.x = __half_as_ushort(h0);
    pk.y = __half_as_ushort(h1);
    pk.z = __half_as_ushort(h2v);
    pk.w = __half_as_ushort(h3);
    *(ushort4*)(g_wqh + (size_t)pos * 4) = pk;
    // den uses the SAME (half-rounded) weights for numerator/denominator consistency
    red4(g_den1 + (size_t)dst * 4,
         __half2float(h0), __half2float(h1), __half2float(h2v), __half2float(h3));
}

// ---------------- FUSED HEAVY: layer-1 agg (fp16 rows, half2 math) + node2 ----------------
__global__ void __launch_bounds__(256) k_agg1n2(
    const float* __restrict__ b1, const float* __restrict__ W2,
    const float* __restrict__ a_src2, const float* __restrict__ a_dst2, int N)
{
    __shared__ float W2s[F1 * OUTCH];   // 6 KB
    __shared__ float b1s[F1];
    __shared__ float as2[OUTCH], ad2[OUTCH];
    int tid = threadIdx.x;
    for (int i = tid; i < F1 * OUTCH; i += 256) W2s[i] = W2[i];
    b1s[tid] = b1[tid];
    if (tid < OUTCH) { as2[tid] = a_src2[tid]; ad2[tid] = a_dst2[tid]; }
    __syncthreads();

    int n = (blockIdx.x * blockDim.x + tid) >> 5;
    if (n >= N) return;
    int lane = tid & 31;
    int c0 = lane * 8;
    int head = lane >> 3;
    int start = g_offs[n], end = g_offs[n + 1];

    __half2 zh = __float2half2_rn(0.f);
    __half2 a0[4] = {zh, zh, zh, zh};
    __half2 a1[4] = {zh, zh, zh, zh};

    int j = start;
    for (; j + 4 <= end; j += 4) {
        int s0 = g_sorted[j], s1 = g_sorted[j + 1], s2 = g_sorted[j + 2], s3 = g_sorted[j + 3];
        unsigned short w0 = g_wqh[(size_t)(j    ) * 4 + head];
        unsigned short w1 = g_wqh[(size_t)(j + 1) * 4 + head];
        unsigned short w2 = g_wqh[(size_t)(j + 2) * 4 + head];
        unsigned short w3 = g_wqh[(size_t)(j + 3) * 4 + head];
        uint4 r0 = *(const uint4*)(g_h1h + (size_t)s0 * F1 + c0);
        uint4 r1 = *(const uint4*)(g_h1h + (size_t)s1 * F1 + c0);
        uint4 r2 = *(const uint4*)(g_h1h + (size_t)s2 * F1 + c0);
        uint4 r3 = *(const uint4*)(g_h1h + (size_t)s3 * F1 + c0);
        acc_row16(a0, r0, __half2half2(__ushort_as_half(w0)));
        acc_row16(a1, r1, __half2half2(__ushort_as_half(w1)));
        acc_row16(a0, r2, __half2half2(__ushort_as_half(w2)));
        acc_row16(a1, r3, __half2half2(__ushort_as_half(w3)));
    }
    for (; j < end; j++) {
        int s0 = g_sorted[j];
        unsigned short w0 = g_wqh[(size_t)j * 4 + head];
        uint4 r0 = *(const uint4*)(g_h1h + (size_t)s0 * F1 + c0);
        acc_row16(a0, r0, __half2half2(__ushort_as_half(w0)));
    }

    // flush half2 accumulators to fp32
    float acc[8];
#pragma unroll
    for (int k = 0; k < 4; k++) {
        float2 t0 = __half22float2(a0[k]);
        float2 t1 = __half22float2(a1[k]);
        acc[2 * k]     = t0.x + t1.x;
        acc[2 * k + 1] = t0.y + t1.y;
    }

    float inv = 1.f / g_den1[(size_t)n * 4 + head];

    float z[OUTCH];
#pragma unroll
    for (int jj = 0; jj < OUTCH; jj++) z[jj] = 0.f;
#pragma unroll
    for (int k = 0; k < 8; k++) {
        float t = fmaf(acc[k], inv, b1s[c0 + k]);
        t = t > 0.f ? t : expm1f(t);      // elu
#pragma unroll
        for (int jj = 0; jj < OUTCH; jj++) z[jj] = fmaf(t, W2s[(c0 + k) * OUTCH + jj], z[jj]);
    }
#pragma unroll
    for (int jj = 0; jj < OUTCH; jj++)
#pragma unroll
        for (int s = 16; s >= 1; s >>= 1)
            z[jj] += __shfl_down_sync(0xffffffffu, z[jj], s);

    if (lane == 0) {
        float as = 0.f, ad = 0.f;
#pragma unroll
        for (int jj = 0; jj < OUTCH; jj++) { as = fmaf(z[jj], as2[jj], as); ad = fmaf(z[jj], ad2[jj], ad); }
        float4* o = (float4*)(g_h2 + (size_t)n * 8);
        o[0] = make_float4(z[0], z[1], z[2], z[3]);
        o[1] = make_float4(z[4], z[5], as, ad);   // [h4, h5, al_src2, al_dst2]
    }
}

// ---------------- layer-2 aggregation + log_softmax (8 lanes per dst) ----------------
__global__ void __launch_bounds__(256) k_agg2(
    const float* __restrict__ b2, float* __restrict__ out, int N)
{
    int n = (blockIdx.x * blockDim.x + threadIdx.x) >> 3;
    if (n >= N) return;
    int sl = threadIdx.x & 7;
    int start = g_offs[n], end = g_offs[n + 1];

    float ald = g_h2[(size_t)n * 8 + 7];
    float acc[OUTCH] = {0.f, 0.f, 0.f, 0.f, 0.f, 0.f};
    float den = 0.f;

    int idx = start + sl;
    for (; idx + 8 < end; idx += 16) {
        int srcA = g_sorted[idx];
        int srcB = g_sorted[idx + 8];
        const float4* hA = (const float4*)(g_h2 + (size_t)srcA * 8);
        const float4* hB = (const float4*)(g_h2 + (size_t)srcB * 8);
        float4 aA = hA[0], bA = hA[1];
        float4 aB = hB[0], bB = hB[1];
        float wA = __expf(lrelu(bA.z + ald));
        float wB = __expf(lrelu(bB.z + ald));
        acc[0] = fmaf(wA, aA.x, acc[0]); acc[1] = fmaf(wA, aA.y, acc[1]);
        acc[2] = fmaf(wA, aA.z, acc[2]); acc[3] = fmaf(wA, aA.w, acc[3]);
        acc[4] = fmaf(wA, bA.x, acc[4]); acc[5] = fmaf(wA, bA.y, acc[5]);
        den += wA;
        acc[0] = fmaf(wB, aB.x, acc[0]); acc[1] = fmaf(wB, aB.y, acc[1]);
        acc[2] = fmaf(wB, aB.z, acc[2]); acc[3] = fmaf(wB, aB.w, acc[3]);
        acc[4] = fmaf(wB, bB.x, acc[4]); acc[5] = fmaf(wB, bB.y, acc[5]);
        den += wB;
    }
    if (idx < end) {
        int src = g_sorted[idx];
        const float4* hp = (const float4*)(g_h2 + (size_t)src * 8);
        float4 a = hp[0], b = hp[1];
        float w = __expf(lrelu(b.z + ald));
        acc[0] = fmaf(w, a.x, acc[0]); acc[1] = fmaf(w, a.y, acc[1]);
        acc[2] = fmaf(w, a.z, acc[2]); acc[3] = fmaf(w, a.w, acc[3]);
        acc[4] = fmaf(w, b.x, acc[4]); acc[5] = fmaf(w, b.y, acc[5]);
        den += w;
    }
#pragma unroll
    for (int s = 4; s >= 1; s >>= 1) {
#pragma unroll
        for (int jj = 0; jj < OUTCH; jj++) acc[jj] += __shfl_down_sync(0xffffffffu, acc[jj], s, 8);
        den += __shfl_down_sync(0xffffffffu, den, s, 8);
    }
    if (sl == 0) {
        float inv = 1.f / den;
        float y[OUTCH], mx = -1e30f;
#pragma unroll
        for (int jj = 0; jj < OUTCH; jj++) {
            y[jj] = fmaf(acc[jj], inv, b2[jj]);
            mx = fmaxf(mx, y[jj]);
        }
        float s = 0.f;
#pragma unroll
        for (int jj = 0; jj < OUTCH; jj++) s += expf(y[jj] - mx);
        float l = mx + logf(s);
#pragma unroll
        for (int jj = 0; jj < OUTCH; jj++) out[(size_t)n * OUTCH + jj] = y[jj] - l;
    }
}

extern "C" void kernel_launch(void* const* d_in, const int* in_sizes, int n_in,
                              void* d_out, int out_size)
{
    const float* x      = (const float*)d_in[0];
    const void*  ei     = d_in[1];
    const float* W1     = (const float*)d_in[2];
    const float* a_src1 = (const float*)d_in[3];
    const float* a_dst1 = (const float*)d_in[4];
    const float* b1     = (const float*)d_in[5];
    const float* W2     = (const float*)d_in[6];
    const float* a_src2 = (const float*)d_in[7];
    const float* a_dst2 = (const float*)d_in[8];
    const float* b2     = (const float*)d_in[9];
    float*       out    = (float*)d_out;

    int N   = in_sizes[0] / INCH;
    int E   = in_sizes[1] / 2;
    int TE  = E + N;
    int NB  = (N + 255) / 256;
    int NBn = (N + 7) / 8;
    int NBe = (TE + 255) / 256;

    void *p_cnt, *p_den;
    cudaGetSymbolAddress(&p_cnt, g_cnt);
    cudaGetSymbolAddress(&p_den, g_den1);
    cudaMemsetAsync(p_cnt, 0, (size_t)N * sizeof(int), 0);
    cudaMemsetAsync(p_den, 0, (size_t)N * 4 * sizeof(float), 0);

    k_node1_hist<<<NBn + NBe, 256>>>(x, W1, a_src1, a_dst1, ei, E, N, NBn);
    k_scan<<<NB, 256>>>(N, NB);
    k_scatter<<<NBe, 256>>>(E, N);
    k_agg1n2<<<(N * 32 + 255) / 256, 256>>>(b1, W2, a_src2, a_dst2, N);
    k_agg2<<<(N * 8 + 255) / 256, 256>>>(b2, out, N);
}

// round 13
// speedup vs baseline: 1.0112x; 1.0112x over previous
#include <cuda_runtime.h>
#include <cuda_fp16.h>
#include <math.h>

#define NMAX    50000
#define EMAX    1700000   // E + N upper bound
#define INCH    7
#define HID     64
#define HEADS   4
#define F1      (HEADS*HID)   // 256
#define OUTCH   6
#define NB_MAX  256       // ceil(NMAX/256) = 196 <= 256

// Scratch (static __device__ — allocation is forbidden)
__device__ __align__(16) __half g_h1h[NMAX * F1]; // layer-1 features, fp16
__device__ __align__(16) float  g_al1[NMAX * 8];  // [al_src1[4], al_dst1[4]] (fp32)
__device__ __align__(16) float  g_den1[NMAX * 4]; // per-head denominators (atomic)
__device__ __align__(16) float  g_h2 [NMAX * 8];  // [h2[6], al_src2, al_dst2]
__device__ __align__(16) unsigned short g_wqh[EMAX * 4]; // per-edge weights, fp16 x 4 heads
__device__ int g_cnt   [NMAX];
__device__ int g_offs  [NMAX + 1];
__device__ int g_cursor[NMAX];
__device__ int g_sorted[EMAX];                    // src ids grouped by dst
__device__ int g_src32 [EMAX];
__device__ int g_dst32 [EMAX];
__device__ int g_pub   [NB_MAX];                  // decoupled-lookback publish slots

__device__ __forceinline__ float lrelu(float v) { return v > 0.f ? v : 0.2f * v; }

__device__ __forceinline__ void red4(float* p, float a, float b, float c, float d) {
    unsigned long long ga = __cvta_generic_to_global(p);
    asm volatile("red.global.add.v4.f32 [%0], {%1,%2,%3,%4};"
                 :: "l"(ga), "f"(a), "f"(b), "f"(c), "f"(d) : "memory");
}

// accumulate one fp16 row (uint4 = 4 x half2) into 4 half2 accumulators
__device__ __forceinline__ void acc_row16(__half2* a, uint4 r, __half2 wh) {
    a[0] = __hfma2(wh, *(__half2*)&r.x, a[0]);
    a[1] = __hfma2(wh, *(__half2*)&r.y, a[1]);
    a[2] = __hfma2(wh, *(__half2*)&r.z, a[2]);
    a[3] = __hfma2(wh, *(__half2*)&r.w, a[3]);
}

// ---------------- FUSED: node transform 1 | edge histogram ----------------
__global__ void __launch_bounds__(256) k_node1_hist(
    const float* __restrict__ x, const float* __restrict__ W1,
    const float* __restrict__ a_src1, const float* __restrict__ a_dst1,
    const void* __restrict__ ei, int E, int N, int NBn)
{
    int tid = threadIdx.x;
    if ((int)blockIdx.x >= NBn) {
        // ---- histogram part ----
        int hb = blockIdx.x - NBn;
        if (hb == 0 && tid < NB_MAX) g_pub[tid] = 0;

        int ok = 1;
        int m = (E * 2 < 64) ? E * 2 : 64;
        if (tid < m) {
            long long v = ((const long long*)ei)[tid];
            ok = (v >= 0 && v < N);
        }
        int is64 = __syncthreads_and(ok);

        int e = hb * 256 + tid;
        int total = E + N;
        if (e >= total) return;
        int dst;
        if (e < E) {
            int src;
            if (is64) {
                const long long* p = (const long long*)ei;
                src = (int)p[e]; dst = (int)p[E + e];
            } else {
                const int* p = (const int*)ei;
                src = p[e]; dst = p[E + e];
            }
            g_src32[e] = src;
            g_dst32[e] = dst;
        } else {
            dst = e - E;
        }
        atomicAdd(&g_cnt[dst], 1);
        return;
    }

    // ---- node transform part ----
    __shared__ float W1s[INCH * F1];
    __shared__ float as1[F1], ad1[F1];
    for (int i = tid; i < INCH * F1; i += 256) W1s[i] = W1[i];
    as1[tid] = a_src1[tid];
    ad1[tid] = a_dst1[tid];
    __syncthreads();

    int n = blockIdx.x * 8 + (tid >> 5);
    if (n >= N) return;
    int lane = tid & 31;
    int c0 = lane * 8;
    int head = lane >> 3;

    float xv = (lane < INCH) ? x[n * INCH + lane] : 0.f;
    float h[8];
#pragma unroll
    for (int j = 0; j < 8; j++) h[j] = 0.f;
#pragma unroll
    for (int i = 0; i < INCH; i++) {
        float xi = __shfl_sync(0xffffffffu, xv, i);
#pragma unroll
        for (int j = 0; j < 8; j++) h[j] = fmaf(xi, W1s[i * F1 + c0 + j], h[j]);
    }
    // store fp16 features (8 halfs = 16B per lane)
    union { __half2 q[4]; uint4 u; } pk;
#pragma unroll
    for (int j = 0; j < 4; j++) pk.q[j] = __floats2half2_rn(h[2 * j], h[2 * j + 1]);
    *(uint4*)(g_h1h + (size_t)n * F1 + c0) = pk.u;

    float ps = 0.f, pd = 0.f;
#pragma unroll
    for (int j = 0; j < 8; j++) {
        ps = fmaf(h[j], as1[c0 + j], ps);
        pd = fmaf(h[j], ad1[c0 + j], pd);
    }
#pragma unroll
    for (int s = 4; s >= 1; s >>= 1) {
        ps += __shfl_down_sync(0xffffffffu, ps, s, 8);
        pd += __shfl_down_sync(0xffffffffu, pd, s, 8);
    }
    if ((lane & 7) == 0) {
        g_al1[n * 8 + head]     = ps;
        g_al1[n * 8 + 4 + head] = pd;
    }
}

// ---------------- CSR scan: single kernel, decoupled lookback ----------------
__global__ void __launch_bounds__(256) k_scan(int N, int NB) {
    int b = blockIdx.x, t = threadIdx.x;
    int i = b * 256 + t;
    int c = (i < N) ? g_cnt[i] : 0;
    int v = c;
#pragma unroll
    for (int s = 1; s < 32; s <<= 1) {
        int u = __shfl_up_sync(0xffffffffu, v, s);
        if ((t & 31) >= s) v += u;
    }
    __shared__ int wsum[8];
    __shared__ int s_agg, s_base;
    if ((t & 31) == 31) wsum[t >> 5] = v;
    __syncthreads();
    if (t == 0) {
        int run = 0;
#pragma unroll
        for (int w = 0; w < 8; w++) { int x = wsum[w]; wsum[w] = run; run += x; }
        s_agg = run;
        atomicExch(&g_pub[b], run + 1);
    }
    __syncthreads();
    int loc = v - c + wsum[t >> 5];

    int pred = 0;
    if (t < b) {
        int x;
        while ((x = atomicAdd(&g_pub[t], 0)) == 0) {}
        pred = x - 1;
    }
#pragma unroll
    for (int s = 16; s >= 1; s >>= 1) pred += __shfl_down_sync(0xffffffffu, pred, s);
    __shared__ int psum[8];
    if ((t & 31) == 0) psum[t >> 5] = pred;
    __syncthreads();
    if (t == 0) {
        int base = 0;
#pragma unroll
        for (int w = 0; w < 8; w++) base += psum[w];
        s_base = base;
    }
    __syncthreads();
    int o = loc + s_base;
    if (i < N) { g_offs[i] = o; g_cursor[i] = o; }
    if (b == NB - 1 && t == 0) g_offs[N] = s_base + s_agg;
}

// ---------------- CSR scatter + weight computation (fp16) + den accumulation ----------------
__global__ void k_scatter(int E, int N) {
    int e = blockIdx.x * blockDim.x + threadIdx.x;
    int total = E + N;
    if (e >= total) return;
    int src, dst;
    if (e < E) { src = g_src32[e]; dst = g_dst32[e]; }
    else       { src = dst = e - E; }
    int pos = atomicAdd(&g_cursor[dst], 1);
    g_sorted[pos] = src;

    float4 s4 = *(const float4*)(g_al1 + (size_t)src * 8);
    float4 d4 = *(const float4*)(g_al1 + (size_t)dst * 8 + 4);
    __half h0 = __float2half_rn(__expf(lrelu(s4.x + d4.x)));
    __half h1 = __float2half_rn(__expf(lrelu(s4.y + d4.y)));
    __half h2v = __float2half_rn(__expf(lrelu(s4.z + d4.z)));
    __half h3 = __float2half_rn(__expf(lrelu(s4.w + d4.w)));
    ushort4 pk;
    pk.x = __half_as_ushort(h0);
    pk.y = __half_as_ushort(h1);
    pk.z = __half_as_ushort(h2v);
    pk.w = __half_as_ushort(h3);
    *(ushort4*)(g_wqh + (size_t)pos * 4) = pk;
    // den uses the SAME (half-rounded) weights for numerator/denominator consistency
    red4(g_den1 + (size_t)dst * 4,
         __half2float(h0), __half2float(h1), __half2float(h2v), __half2float(h3));
}

// ---------------- FUSED HEAVY: layer-1 agg (fp16 rows, 2-edge unroll) + node2 ----------------
__global__ void __launch_bounds__(256, 6) k_agg1n2(
    const float* __restrict__ b1, const float* __restrict__ W2,
    const float* __restrict__ a_src2, const float* __restrict__ a_dst2, int N)
{
    __shared__ float W2s[F1 * OUTCH];   // 6 KB
    __shared__ float b1s[F1];
    __shared__ float as2[OUTCH], ad2[OUTCH];
    int tid = threadIdx.x;
    for (int i = tid; i < F1 * OUTCH; i += 256) W2s[i] = W2[i];
    b1s[tid] = b1[tid];
    if (tid < OUTCH) { as2[tid] = a_src2[tid]; ad2[tid] = a_dst2[tid]; }
    __syncthreads();

    int n = (blockIdx.x * blockDim.x + tid) >> 5;
    if (n >= N) return;
    int lane = tid & 31;
    int c0 = lane * 8;
    int head = lane >> 3;
    int start = g_offs[n], end = g_offs[n + 1];

    __half2 zh = __float2half2_rn(0.f);
    __half2 a0[4] = {zh, zh, zh, zh};
    __half2 a1[4] = {zh, zh, zh, zh};

    int j = start;
    for (; j + 2 <= end; j += 2) {
        int s0 = g_sorted[j], s1 = g_sorted[j + 1];
        unsigned short w0 = g_wqh[(size_t)(j    ) * 4 + head];
        unsigned short w1 = g_wqh[(size_t)(j + 1) * 4 + head];
        uint4 r0 = *(const uint4*)(g_h1h + (size_t)s0 * F1 + c0);
        uint4 r1 = *(const uint4*)(g_h1h + (size_t)s1 * F1 + c0);
        acc_row16(a0, r0, __half2half2(__ushort_as_half(w0)));
        acc_row16(a1, r1, __half2half2(__ushort_as_half(w1)));
    }
    if (j < end) {
        int s0 = g_sorted[j];
        unsigned short w0 = g_wqh[(size_t)j * 4 + head];
        uint4 r0 = *(const uint4*)(g_h1h + (size_t)s0 * F1 + c0);
        acc_row16(a0, r0, __half2half2(__ushort_as_half(w0)));
    }

    // flush half2 accumulators to fp32
    float acc[8];
#pragma unroll
    for (int k = 0; k < 4; k++) {
        float2 t0 = __half22float2(a0[k]);
        float2 t1 = __half22float2(a1[k]);
        acc[2 * k]     = t0.x + t1.x;
        acc[2 * k + 1] = t0.y + t1.y;
    }

    float inv = 1.f / g_den1[(size_t)n * 4 + head];

    float z[OUTCH];
#pragma unroll
    for (int jj = 0; jj < OUTCH; jj++) z[jj] = 0.f;
#pragma unroll
    for (int k = 0; k < 8; k++) {
        float t = fmaf(acc[k], inv, b1s[c0 + k]);
        t = t > 0.f ? t : expm1f(t);      // elu
#pragma unroll
        for (int jj = 0; jj < OUTCH; jj++) z[jj] = fmaf(t, W2s[(c0 + k) * OUTCH + jj], z[jj]);
    }
#pragma unroll
    for (int jj = 0; jj < OUTCH; jj++)
#pragma unroll
        for (int s = 16; s >= 1; s >>= 1)
            z[jj] += __shfl_down_sync(0xffffffffu, z[jj], s);

    if (lane == 0) {
        float as = 0.f, ad = 0.f;
#pragma unroll
        for (int jj = 0; jj < OUTCH; jj++) { as = fmaf(z[jj], as2[jj], as); ad = fmaf(z[jj], ad2[jj], ad); }
        float4* o = (float4*)(g_h2 + (size_t)n * 8);
        o[0] = make_float4(z[0], z[1], z[2], z[3]);
        o[1] = make_float4(z[4], z[5], as, ad);   // [h4, h5, al_src2, al_dst2]
    }
}

// ---------------- layer-2 aggregation + log_softmax (8 lanes per dst) ----------------
__global__ void __launch_bounds__(256) k_agg2(
    const float* __restrict__ b2, float* __restrict__ out, int N)
{
    int n = (blockIdx.x * blockDim.x + threadIdx.x) >> 3;
    if (n >= N) return;
    int sl = threadIdx.x & 7;
    int start = g_offs[n], end = g_offs[n + 1];

    float ald = g_h2[(size_t)n * 8 + 7];
    float acc[OUTCH] = {0.f, 0.f, 0.f, 0.f, 0.f, 0.f};
    float den = 0.f;

    int idx = start + sl;
    for (; idx + 8 < end; idx += 16) {
        int srcA = g_sorted[idx];
        int srcB = g_sorted[idx + 8];
        const float4* hA = (const float4*)(g_h2 + (size_t)srcA * 8);
        const float4* hB = (const float4*)(g_h2 + (size_t)srcB * 8);
        float4 aA = hA[0], bA = hA[1];
        float4 aB = hB[0], bB = hB[1];
        float wA = __expf(lrelu(bA.z + ald));
        float wB = __expf(lrelu(bB.z + ald));
        acc[0] = fmaf(wA, aA.x, acc[0]); acc[1] = fmaf(wA, aA.y, acc[1]);
        acc[2] = fmaf(wA, aA.z, acc[2]); acc[3] = fmaf(wA, aA.w, acc[3]);
        acc[4] = fmaf(wA, bA.x, acc[4]); acc[5] = fmaf(wA, bA.y, acc[5]);
        den += wA;
        acc[0] = fmaf(wB, aB.x, acc[0]); acc[1] = fmaf(wB, aB.y, acc[1]);
        acc[2] = fmaf(wB, aB.z, acc[2]); acc[3] = fmaf(wB, aB.w, acc[3]);
        acc[4] = fmaf(wB, bB.x, acc[4]); acc[5] = fmaf(wB, bB.y, acc[5]);
        den += wB;
    }
    if (idx < end) {
        int src = g_sorted[idx];
        const float4* hp = (const float4*)(g_h2 + (size_t)src * 8);
        float4 a = hp[0], b = hp[1];
        float w = __expf(lrelu(b.z + ald));
        acc[0] = fmaf(w, a.x, acc[0]); acc[1] = fmaf(w, a.y, acc[1]);
        acc[2] = fmaf(w, a.z, acc[2]); acc[3] = fmaf(w, a.w, acc[3]);
        acc[4] = fmaf(w, b.x, acc[4]); acc[5] = fmaf(w, b.y, acc[5]);
        den += w;
    }
#pragma unroll
    for (int s = 4; s >= 1; s >>= 1) {
#pragma unroll
        for (int jj = 0; jj < OUTCH; jj++) acc[jj] += __shfl_down_sync(0xffffffffu, acc[jj], s, 8);
        den += __shfl_down_sync(0xffffffffu, den, s, 8);
    }
    if (sl == 0) {
        float inv = 1.f / den;
        float y[OUTCH], mx = -1e30f;
#pragma unroll
        for (int jj = 0; jj < OUTCH; jj++) {
            y[jj] = fmaf(acc[jj], inv, b2[jj]);
            mx = fmaxf(mx, y[jj]);
        }
        float s = 0.f;
#pragma unroll
        for (int jj = 0; jj < OUTCH; jj++) s += expf(y[jj] - mx);
        float l = mx + logf(s);
#pragma unroll
        for (int jj = 0; jj < OUTCH; jj++) out[(size_t)n * OUTCH + jj] = y[jj] - l;
    }
}

extern "C" void kernel_launch(void* const* d_in, const int* in_sizes, int n_in,
                              void* d_out, int out_size)
{
    const float* x      = (const float*)d_in[0];
    const void*  ei     = d_in[1];
    const float* W1     = (const float*)d_in[2];
    const float* a_src1 = (const float*)d_in[3];
    const float* a_dst1 = (const float*)d_in[4];
    const float* b1     = (const float*)d_in[5];
    const float* W2     = (const float*)d_in[6];
    const float* a_src2 = (const float*)d_in[7];
    const float* a_dst2 = (const float*)d_in[8];
    const float* b2     = (const float*)d_in[9];
    float*       out    = (float*)d_out;

    int N   = in_sizes[0] / INCH;
    int E   = in_sizes[1] / 2;
    int TE  = E + N;
    int NB  = (N + 255) / 256;
    int NBn = (N + 7) / 8;
    int NBe = (TE + 255) / 256;

    void *p_cnt, *p_den;
    cudaGetSymbolAddress(&p_cnt, g_cnt);
    cudaGetSymbolAddress(&p_den, g_den1);
    cudaMemsetAsync(p_cnt, 0, (size_t)N * sizeof(int), 0);
    cudaMemsetAsync(p_den, 0, (size_t)N * 4 * sizeof(float), 0);

    k_node1_hist<<<NBn + NBe, 256>>>(x, W1, a_src1, a_dst1, ei, E, N, NBn);
    k_scan<<<NB, 256>>>(N, NB);
    k_scatter<<<NBe, 256>>>(E, N);
    k_agg1n2<<<(N * 32 + 255) / 256, 256>>>(b1, W2, a_src2, a_dst2, N);
    k_agg2<<<(N * 8 + 255) / 256, 256>>>(b2, out, N);
}

// round 14
// speedup vs baseline: 1.0908x; 1.0787x over previous
#include <cuda_runtime.h>
#include <cuda_fp16.h>
#include <math.h>

#define NMAX    50000
#define EMAX    1700000   // E + N upper bound
#define INCH    7
#define HID     64
#define HEADS   4
#define F1      (HEADS*HID)   // 256
#define OUTCH   6
#define NB_MAX  256       // ceil(NMAX/256) = 196 <= 256

// Scratch (static __device__ — allocation is forbidden)
__device__ __align__(16) unsigned char g_h1q[NMAX * F1]; // layer-1 features, fp8 e4m3
__device__ __align__(16) float  g_al1[NMAX * 8];  // [al_src1[4], al_dst1[4]] (fp32)
__device__ __align__(16) float  g_den1[NMAX * 4]; // per-head denominators (atomic)
__device__ __align__(16) float  g_h2 [NMAX * 8];  // [h2[6], al_src2, al_dst2]
__device__ __align__(16) unsigned short g_wqh[EMAX * 4]; // per-edge weights, fp16 x 4 heads
__device__ int g_cnt   [NMAX];
__device__ int g_offs  [NMAX + 1];
__device__ int g_cursor[NMAX];
__device__ int g_sorted[EMAX];                    // src ids grouped by dst
__device__ int g_src32 [EMAX];
__device__ int g_dst32 [EMAX];
__device__ int g_pub   [NB_MAX];                  // decoupled-lookback publish slots

__device__ __forceinline__ float lrelu(float v) { return v > 0.f ? v : 0.2f * v; }

__device__ __forceinline__ unsigned short pack_e4m3(float lo, float hi) {
    unsigned short r;
    asm("cvt.rn.satfinite.e4m3x2.f32 %0, %1, %2;" : "=h"(r) : "f"(hi), "f"(lo));
    return r;
}
// e4m3x2 -> half2 (single cvt)
__device__ __forceinline__ __half2 cvt8h2(unsigned int v) {
    unsigned int h;
    asm("cvt.rn.f16x2.e4m3x2 %0, %1;" : "=r"(h) : "h"((unsigned short)v));
    return *(__half2*)&h;
}

__device__ __forceinline__ void red4(float* p, float a, float b, float c, float d) {
    unsigned long long ga = __cvta_generic_to_global(p);
    asm volatile("red.global.add.v4.f32 [%0], {%1,%2,%3,%4};"
                 :: "l"(ga), "f"(a), "f"(b), "f"(c), "f"(d) : "memory");
}

// accumulate one fp8 row into 4 half2 accumulators
__device__ __forceinline__ void acc_row_h2(__half2* a, uint2 r, __half2 wh) {
    a[0] = __hfma2(wh, cvt8h2(r.x & 0xffff), a[0]);
    a[1] = __hfma2(wh, cvt8h2(r.x >> 16),    a[1]);
    a[2] = __hfma2(wh, cvt8h2(r.y & 0xffff), a[2]);
    a[3] = __hfma2(wh, cvt8h2(r.y >> 16),    a[3]);
}

// helper: compute + store edge weights for one placed edge
__device__ __forceinline__ void place_edge(int src, int dst) {
    int pos = atomicAdd(&g_cursor[dst], 1);
    g_sorted[pos] = src;
    float4 s4 = *(const float4*)(g_al1 + (size_t)src * 8);
    float4 d4 = *(const float4*)(g_al1 + (size_t)dst * 8 + 4);
    __half h0 = __float2half_rn(__expf(lrelu(s4.x + d4.x)));
    __half h1 = __float2half_rn(__expf(lrelu(s4.y + d4.y)));
    __half h2v = __float2half_rn(__expf(lrelu(s4.z + d4.z)));
    __half h3 = __float2half_rn(__expf(lrelu(s4.w + d4.w)));
    ushort4 pk;
    pk.x = __half_as_ushort(h0);
    pk.y = __half_as_ushort(h1);
    pk.z = __half_as_ushort(h2v);
    pk.w = __half_as_ushort(h3);
    *(ushort4*)(g_wqh + (size_t)pos * 4) = pk;
    red4(g_den1 + (size_t)dst * 4,
         __half2float(h0), __half2float(h1), __half2float(h2v), __half2float(h3));
}

// ---------------- FUSED: node transform 1 | edge histogram (2 edges/thread) ----------------
__global__ void __launch_bounds__(256) k_node1_hist(
    const float* __restrict__ x, const float* __restrict__ W1,
    const float* __restrict__ a_src1, const float* __restrict__ a_dst1,
    const void* __restrict__ ei, int E, int N, int NBn)
{
    int tid = threadIdx.x;
    if ((int)blockIdx.x >= NBn) {
        // ---- histogram part: 512 edges per block ----
        int hb = blockIdx.x - NBn;
        if (hb == 0 && tid < NB_MAX) g_pub[tid] = 0;

        int ok = 1;
        int m = (E * 2 < 64) ? E * 2 : 64;
        if (tid < m) {
            long long v = ((const long long*)ei)[tid];
            ok = (v >= 0 && v < N);
        }
        int is64 = __syncthreads_and(ok);

        int total = E + N;
        int base = hb * 512 + tid;
#pragma unroll
        for (int q = 0; q < 2; q++) {
            int e = base + q * 256;
            if (e >= total) break;
            int dst;
            if (e < E) {
                int src;
                if (is64) {
                    const long long* p = (const long long*)ei;
                    src = (int)p[e]; dst = (int)p[E + e];
                } else {
                    const int* p = (const int*)ei;
                    src = p[e]; dst = p[E + e];
                }
                g_src32[e] = src;
                g_dst32[e] = dst;
            } else {
                dst = e - E;
            }
            atomicAdd(&g_cnt[dst], 1);
        }
        return;
    }

    // ---- node transform part ----
    __shared__ float W1s[INCH * F1];
    __shared__ float as1[F1], ad1[F1];
    for (int i = tid; i < INCH * F1; i += 256) W1s[i] = W1[i];
    as1[tid] = a_src1[tid];
    ad1[tid] = a_dst1[tid];
    __syncthreads();

    int n = blockIdx.x * 8 + (tid >> 5);
    if (n >= N) return;
    int lane = tid & 31;
    int c0 = lane * 8;
    int head = lane >> 3;

    float xv = (lane < INCH) ? x[n * INCH + lane] : 0.f;
    float h[8];
#pragma unroll
    for (int j = 0; j < 8; j++) h[j] = 0.f;
#pragma unroll
    for (int i = 0; i < INCH; i++) {
        float xi = __shfl_sync(0xffffffffu, xv, i);
#pragma unroll
        for (int j = 0; j < 8; j++) h[j] = fmaf(xi, W1s[i * F1 + c0 + j], h[j]);
    }
    unsigned short p0 = pack_e4m3(h[0], h[1]);
    unsigned short p1 = pack_e4m3(h[2], h[3]);
    unsigned short p2 = pack_e4m3(h[4], h[5]);
    unsigned short p3 = pack_e4m3(h[6], h[7]);
    uint2 pk;
    pk.x = (unsigned)p0 | ((unsigned)p1 << 16);
    pk.y = (unsigned)p2 | ((unsigned)p3 << 16);
    *(uint2*)(g_h1q + (size_t)n * F1 + c0) = pk;

    float ps = 0.f, pd = 0.f;
#pragma unroll
    for (int j = 0; j < 8; j++) {
        ps = fmaf(h[j], as1[c0 + j], ps);
        pd = fmaf(h[j], ad1[c0 + j], pd);
    }
#pragma unroll
    for (int s = 4; s >= 1; s >>= 1) {
        ps += __shfl_down_sync(0xffffffffu, ps, s, 8);
        pd += __shfl_down_sync(0xffffffffu, pd, s, 8);
    }
    if ((lane & 7) == 0) {
        g_al1[n * 8 + head]     = ps;
        g_al1[n * 8 + 4 + head] = pd;
    }
}

// ---------------- CSR scan: single kernel, decoupled lookback ----------------
__global__ void __launch_bounds__(256) k_scan(int N, int NB) {
    int b = blockIdx.x, t = threadIdx.x;
    int i = b * 256 + t;
    int c = (i < N) ? g_cnt[i] : 0;
    int v = c;
#pragma unroll
    for (int s = 1; s < 32; s <<= 1) {
        int u = __shfl_up_sync(0xffffffffu, v, s);
        if ((t & 31) >= s) v += u;
    }
    __shared__ int wsum[8];
    __shared__ int s_agg, s_base;
    if ((t & 31) == 31) wsum[t >> 5] = v;
    __syncthreads();
    if (t == 0) {
        int run = 0;
#pragma unroll
        for (int w = 0; w < 8; w++) { int x = wsum[w]; wsum[w] = run; run += x; }
        s_agg = run;
        atomicExch(&g_pub[b], run + 1);
    }
    __syncthreads();
    int loc = v - c + wsum[t >> 5];

    int pred = 0;
    if (t < b) {
        int x;
        while ((x = atomicAdd(&g_pub[t], 0)) == 0) {}
        pred = x - 1;
    }
#pragma unroll
    for (int s = 16; s >= 1; s >>= 1) pred += __shfl_down_sync(0xffffffffu, pred, s);
    __shared__ int psum[8];
    if ((t & 31) == 0) psum[t >> 5] = pred;
    __syncthreads();
    if (t == 0) {
        int base = 0;
#pragma unroll
        for (int w = 0; w < 8; w++) base += psum[w];
        s_base = base;
    }
    __syncthreads();
    int o = loc + s_base;
    if (i < N) { g_offs[i] = o; g_cursor[i] = o; }
    if (b == NB - 1 && t == 0) g_offs[N] = s_base + s_agg;
}

// ---------------- CSR scatter + weights + den (2 edges/thread for MLP) ----------------
__global__ void __launch_bounds__(256) k_scatter(int E, int N) {
    int total = E + N;
    int base = blockIdx.x * 512 + threadIdx.x;

    int e0 = base, e1 = base + 256;
    bool v0 = e0 < total, v1 = e1 < total;
    int s0 = 0, d0 = 0, s1 = 0, d1 = 0;
    if (v0) {
        if (e0 < E) { s0 = g_src32[e0]; d0 = g_dst32[e0]; }
        else        { s0 = d0 = e0 - E; }
    }
    if (v1) {
        if (e1 < E) { s1 = g_src32[e1]; d1 = g_dst32[e1]; }
        else        { s1 = d1 = e1 - E; }
    }
    if (v0) place_edge(s0, d0);
    if (v1) place_edge(s1, d1);
}

// ---------------- FUSED HEAVY: layer-1 agg (fp8, half2 math, 2 acc sets) + node2 ----------------
__global__ void __launch_bounds__(256) k_agg1n2(
    const float* __restrict__ b1, const float* __restrict__ W2,
    const float* __restrict__ a_src2, const float* __restrict__ a_dst2, int N)
{
    __shared__ float W2s[F1 * OUTCH];   // 6 KB
    __shared__ float b1s[F1];
    __shared__ float as2[OUTCH], ad2[OUTCH];
    int tid = threadIdx.x;
    for (int i = tid; i < F1 * OUTCH; i += 256) W2s[i] = W2[i];
    b1s[tid] = b1[tid];
    if (tid < OUTCH) { as2[tid] = a_src2[tid]; ad2[tid] = a_dst2[tid]; }
    __syncthreads();

    int n = (blockIdx.x * blockDim.x + tid) >> 5;
    if (n >= N) return;
    int lane = tid & 31;
    int c0 = lane * 8;
    int head = lane >> 3;
    int start = g_offs[n], end = g_offs[n + 1];

    __half2 zh = __float2half2_rn(0.f);
    __half2 a0[4] = {zh, zh, zh, zh};
    __half2 a1[4] = {zh, zh, zh, zh};

    int j = start;
    for (; j + 4 <= end; j += 4) {
        int s0 = g_sorted[j], s1 = g_sorted[j + 1], s2 = g_sorted[j + 2], s3 = g_sorted[j + 3];
        unsigned short w0 = g_wqh[(size_t)(j    ) * 4 + head];
        unsigned short w1 = g_wqh[(size_t)(j + 1) * 4 + head];
        unsigned short w2 = g_wqh[(size_t)(j + 2) * 4 + head];
        unsigned short w3 = g_wqh[(size_t)(j + 3) * 4 + head];
        uint2 r0 = *(const uint2*)(g_h1q + (size_t)s0 * F1 + c0);
        uint2 r1 = *(const uint2*)(g_h1q + (size_t)s1 * F1 + c0);
        uint2 r2 = *(const uint2*)(g_h1q + (size_t)s2 * F1 + c0);
        uint2 r3 = *(const uint2*)(g_h1q + (size_t)s3 * F1 + c0);
        acc_row_h2(a0, r0, __half2half2(__ushort_as_half(w0)));
        acc_row_h2(a1, r1, __half2half2(__ushort_as_half(w1)));
        acc_row_h2(a0, r2, __half2half2(__ushort_as_half(w2)));
        acc_row_h2(a1, r3, __half2half2(__ushort_as_half(w3)));
    }
    for (; j < end; j++) {
        int s0 = g_sorted[j];
        unsigned short w0 = g_wqh[(size_t)j * 4 + head];
        uint2 r0 = *(const uint2*)(g_h1q + (size_t)s0 * F1 + c0);
        acc_row_h2(a0, r0, __half2half2(__ushort_as_half(w0)));
    }

    // flush half2 accumulators to fp32
    float acc[8];
#pragma unroll
    for (int k = 0; k < 4; k++) {
        float2 t0 = __half22float2(a0[k]);
        float2 t1 = __half22float2(a1[k]);
        acc[2 * k]     = t0.x + t1.x;
        acc[2 * k + 1] = t0.y + t1.y;
    }

    float inv = 1.f / g_den1[(size_t)n * 4 + head];

    float z[OUTCH];
#pragma unroll
    for (int jj = 0; jj < OUTCH; jj++) z[jj] = 0.f;
#pragma unroll
    for (int k = 0; k < 8; k++) {
        float t = fmaf(acc[k], inv, b1s[c0 + k]);
        t = t > 0.f ? t : expm1f(t);      // elu
#pragma unroll
        for (int jj = 0; jj < OUTCH; jj++) z[jj] = fmaf(t, W2s[(c0 + k) * OUTCH + jj], z[jj]);
    }
#pragma unroll
    for (int jj = 0; jj < OUTCH; jj++)
#pragma unroll
        for (int s = 16; s >= 1; s >>= 1)
            z[jj] += __shfl_down_sync(0xffffffffu, z[jj], s);

    if (lane == 0) {
        float as = 0.f, ad = 0.f;
#pragma unroll
        for (int jj = 0; jj < OUTCH; jj++) { as = fmaf(z[jj], as2[jj], as); ad = fmaf(z[jj], ad2[jj], ad); }
        float4* o = (float4*)(g_h2 + (size_t)n * 8);
        o[0] = make_float4(z[0], z[1], z[2], z[3]);
        o[1] = make_float4(z[4], z[5], as, ad);   // [h4, h5, al_src2, al_dst2]
    }
}

// ---------------- layer-2 aggregation + log_softmax (8 lanes per dst) ----------------
__global__ void __launch_bounds__(256) k_agg2(
    const float* __restrict__ b2, float* __restrict__ out, int N)
{
    int n = (blockIdx.x * blockDim.x + threadIdx.x) >> 3;
    if (n >= N) return;
    int sl = threadIdx.x & 7;
    int start = g_offs[n], end = g_offs[n + 1];

    float ald = g_h2[(size_t)n * 8 + 7];
    float acc[OUTCH] = {0.f, 0.f, 0.f, 0.f, 0.f, 0.f};
    float den = 0.f;

    int idx = start + sl;
    for (; idx + 8 < end; idx += 16) {
        int srcA = g_sorted[idx];
        int srcB = g_sorted[idx + 8];
        const float4* hA = (const float4*)(g_h2 + (size_t)srcA * 8);
        const float4* hB = (const float4*)(g_h2 + (size_t)srcB * 8);
        float4 aA = hA[0], bA = hA[1];
        float4 aB = hB[0], bB = hB[1];
        float wA = __expf(lrelu(bA.z + ald));
        float wB = __expf(lrelu(bB.z + ald));
        acc[0] = fmaf(wA, aA.x, acc[0]); acc[1] = fmaf(wA, aA.y, acc[1]);
        acc[2] = fmaf(wA, aA.z, acc[2]); acc[3] = fmaf(wA, aA.w, acc[3]);
        acc[4] = fmaf(wA, bA.x, acc[4]); acc[5] = fmaf(wA, bA.y, acc[5]);
        den += wA;
        acc[0] = fmaf(wB, aB.x, acc[0]); acc[1] = fmaf(wB, aB.y, acc[1]);
        acc[2] = fmaf(wB, aB.z, acc[2]); acc[3] = fmaf(wB, aB.w, acc[3]);
        acc[4] = fmaf(wB, bB.x, acc[4]); acc[5] = fmaf(wB, bB.y, acc[5]);
        den += wB;
    }
    if (idx < end) {
        int src = g_sorted[idx];
        const float4* hp = (const float4*)(g_h2 + (size_t)src * 8);
        float4 a = hp[0], b = hp[1];
        float w = __expf(lrelu(b.z + ald));
        acc[0] = fmaf(w, a.x, acc[0]); acc[1] = fmaf(w, a.y, acc[1]);
        acc[2] = fmaf(w, a.z, acc[2]); acc[3] = fmaf(w, a.w, acc[3]);
        acc[4] = fmaf(w, b.x, acc[4]); acc[5] = fmaf(w, b.y, acc[5]);
        den += w;
    }
#pragma unroll
    for (int s = 4; s >= 1; s >>= 1) {
#pragma unroll
        for (int jj = 0; jj < OUTCH; jj++) acc[jj] += __shfl_down_sync(0xffffffffu, acc[jj], s, 8);
        den += __shfl_down_sync(0xffffffffu, den, s, 8);
    }
    if (sl == 0) {
        float inv = 1.f / den;
        float y[OUTCH], mx = -1e30f;
#pragma unroll
        for (int jj = 0; jj < OUTCH; jj++) {
            y[jj] = fmaf(acc[jj], inv, b2[jj]);
            mx = fmaxf(mx, y[jj]);
        }
        float s = 0.f;
#pragma unroll
        for (int jj = 0; jj < OUTCH; jj++) s += expf(y[jj] - mx);
        float l = mx + logf(s);
#pragma unroll
        for (int jj = 0; jj < OUTCH; jj++) out[(size_t)n * OUTCH + jj] = y[jj] - l;
    }
}

extern "C" void kernel_launch(void* const* d_in, const int* in_sizes, int n_in,
                              void* d_out, int out_size)
{
    const float* x      = (const float*)d_in[0];
    const void*  ei     = d_in[1];
    const float* W1     = (const float*)d_in[2];
    const float* a_src1 = (const float*)d_in[3];
    const float* a_dst1 = (const float*)d_in[4];
    const float* b1     = (const float*)d_in[5];
    const float* W2     = (const float*)d_in[6];
    const float* a_src2 = (const float*)d_in[7];
    const float* a_dst2 = (const float*)d_in[8];
    const float* b2     = (const float*)d_in[9];
    float*       out    = (float*)d_out;

    int N    = in_sizes[0] / INCH;
    int E    = in_sizes[1] / 2;
    int TE   = E + N;
    int NB   = (N + 255) / 256;
    int NBn  = (N + 7) / 8;
    int NBe2 = (TE + 511) / 512;

    void *p_cnt, *p_den;
    cudaGetSymbolAddress(&p_cnt, g_cnt);
    cudaGetSymbolAddress(&p_den, g_den1);
    cudaMemsetAsync(p_cnt, 0, (size_t)N * sizeof(int), 0);
    cudaMemsetAsync(p_den, 0, (size_t)N * 4 * sizeof(float), 0);

    k_node1_hist<<<NBn + NBe2, 256>>>(x, W1, a_src1, a_dst1, ei, E, N, NBn);
    k_scan<<<NB, 256>>>(N, NB);
    k_scatter<<<NBe2, 256>>>(E, N);
    k_agg1n2<<<(N * 32 + 255) / 256, 256>>>(b1, W2, a_src2, a_dst2, N);
    k_agg2<<<(N * 8 + 255) / 256, 256>>>(b2, out, N);
}

// round 15
// speedup vs baseline: 1.1068x; 1.0147x over previous
#include <cuda_runtime.h>
#include <cuda_fp16.h>
#include <math.h>

#define NMAX    50000
#define EMAX    1700000   // E + N upper bound
#define INCH    7
#define HID     64
#define HEADS   4
#define F1      (HEADS*HID)   // 256
#define OUTCH   6
#define NB_MAX  256       // ceil(NMAX/256) = 196 <= 256

// Scratch (static __device__ — allocation is forbidden)
__device__ __align__(16) unsigned char g_h1q[NMAX * F1]; // layer-1 features, fp8 e4m3
__device__ __align__(16) float  g_al1[NMAX * 8];  // [al_src1[4], al_dst1[4]] (fp32)
__device__ __align__(16) float  g_den1[NMAX * 4]; // per-head denominators (atomic)
__device__ __align__(16) float  g_h2 [NMAX * 8];  // [h2[6], al_src2, al_dst2]
__device__ __align__(16) unsigned short g_wqh[EMAX * 4]; // per-edge weights, fp16 x 4 heads
__device__ int g_cnt   [NMAX];
__device__ int g_offs  [NMAX + 1];
__device__ int g_cursor[NMAX];
__device__ __align__(16) int g_sorted[EMAX];      // src ids grouped by dst
__device__ int g_src32 [EMAX];
__device__ int g_dst32 [EMAX];
__device__ int g_pub   [NB_MAX];                  // decoupled-lookback publish slots

__device__ __forceinline__ float lrelu(float v) { return v > 0.f ? v : 0.2f * v; }

__device__ __forceinline__ unsigned short pack_e4m3(float lo, float hi) {
    unsigned short r;
    asm("cvt.rn.satfinite.e4m3x2.f32 %0, %1, %2;" : "=h"(r) : "f"(hi), "f"(lo));
    return r;
}
// e4m3x2 -> half2 (single cvt)
__device__ __forceinline__ __half2 cvt8h2(unsigned int v) {
    unsigned int h;
    asm("cvt.rn.f16x2.e4m3x2 %0, %1;" : "=r"(h) : "h"((unsigned short)v));
    return *(__half2*)&h;
}

__device__ __forceinline__ void red4(float* p, float a, float b, float c, float d) {
    unsigned long long ga = __cvta_generic_to_global(p);
    asm volatile("red.global.add.v4.f32 [%0], {%1,%2,%3,%4};"
                 :: "l"(ga), "f"(a), "f"(b), "f"(c), "f"(d) : "memory");
}

// accumulate one fp8 row into 4 half2 accumulators
__device__ __forceinline__ void acc_row_h2(__half2* a, uint2 r, __half2 wh) {
    a[0] = __hfma2(wh, cvt8h2(r.x & 0xffff), a[0]);
    a[1] = __hfma2(wh, cvt8h2(r.x >> 16),    a[1]);
    a[2] = __hfma2(wh, cvt8h2(r.y & 0xffff), a[2]);
    a[3] = __hfma2(wh, cvt8h2(r.y >> 16),    a[3]);
}

// helper: compute + store edge weights for one placed edge
__device__ __forceinline__ void place_edge(int src, int dst) {
    int pos = atomicAdd(&g_cursor[dst], 1);
    g_sorted[pos] = src;
    float4 s4 = *(const float4*)(g_al1 + (size_t)src * 8);
    float4 d4 = *(const float4*)(g_al1 + (size_t)dst * 8 + 4);
    __half h0 = __float2half_rn(__expf(lrelu(s4.x + d4.x)));
    __half h1 = __float2half_rn(__expf(lrelu(s4.y + d4.y)));
    __half h2v = __float2half_rn(__expf(lrelu(s4.z + d4.z)));
    __half h3 = __float2half_rn(__expf(lrelu(s4.w + d4.w)));
    ushort4 pk;
    pk.x = __half_as_ushort(h0);
    pk.y = __half_as_ushort(h1);
    pk.z = __half_as_ushort(h2v);
    pk.w = __half_as_ushort(h3);
    *(ushort4*)(g_wqh + (size_t)pos * 4) = pk;
    red4(g_den1 + (size_t)dst * 4,
         __half2float(h0), __half2float(h1), __half2float(h2v), __half2float(h3));
}

// ---------------- FUSED: node transform 1 | edge histogram (2 edges/thread) ----------------
__global__ void __launch_bounds__(256) k_node1_hist(
    const float* __restrict__ x, const float* __restrict__ W1,
    const float* __restrict__ a_src1, const float* __restrict__ a_dst1,
    const void* __restrict__ ei, int E, int N, int NBn)
{
    int tid = threadIdx.x;
    if ((int)blockIdx.x >= NBn) {
        // ---- histogram part: 512 edges per block ----
        int hb = blockIdx.x - NBn;
        if (hb == 0 && tid < NB_MAX) g_pub[tid] = 0;

        int ok = 1;
        int m = (E * 2 < 64) ? E * 2 : 64;
        if (tid < m) {
            long long v = ((const long long*)ei)[tid];
            ok = (v >= 0 && v < N);
        }
        int is64 = __syncthreads_and(ok);

        int total = E + N;
        int base = hb * 512 + tid;
#pragma unroll
        for (int q = 0; q < 2; q++) {
            int e = base + q * 256;
            if (e >= total) break;
            int dst;
            if (e < E) {
                int src;
                if (is64) {
                    const long long* p = (const long long*)ei;
                    src = (int)p[e]; dst = (int)p[E + e];
                } else {
                    const int* p = (const int*)ei;
                    src = p[e]; dst = p[E + e];
                }
                g_src32[e] = src;
                g_dst32[e] = dst;
            } else {
                dst = e - E;
            }
            atomicAdd(&g_cnt[dst], 1);
        }
        return;
    }

    // ---- node transform part ----
    __shared__ float W1s[INCH * F1];
    __shared__ float as1[F1], ad1[F1];
    for (int i = tid; i < INCH * F1; i += 256) W1s[i] = W1[i];
    as1[tid] = a_src1[tid];
    ad1[tid] = a_dst1[tid];
    __syncthreads();

    int n = blockIdx.x * 8 + (tid >> 5);
    if (n >= N) return;
    int lane = tid & 31;
    int c0 = lane * 8;
    int head = lane >> 3;

    float xv = (lane < INCH) ? x[n * INCH + lane] : 0.f;
    float h[8];
#pragma unroll
    for (int j = 0; j < 8; j++) h[j] = 0.f;
#pragma unroll
    for (int i = 0; i < INCH; i++) {
        float xi = __shfl_sync(0xffffffffu, xv, i);
#pragma unroll
        for (int j = 0; j < 8; j++) h[j] = fmaf(xi, W1s[i * F1 + c0 + j], h[j]);
    }
    unsigned short p0 = pack_e4m3(h[0], h[1]);
    unsigned short p1 = pack_e4m3(h[2], h[3]);
    unsigned short p2 = pack_e4m3(h[4], h[5]);
    unsigned short p3 = pack_e4m3(h[6], h[7]);
    uint2 pk;
    pk.x = (unsigned)p0 | ((unsigned)p1 << 16);
    pk.y = (unsigned)p2 | ((unsigned)p3 << 16);
    *(uint2*)(g_h1q + (size_t)n * F1 + c0) = pk;

    float ps = 0.f, pd = 0.f;
#pragma unroll
    for (int j = 0; j < 8; j++) {
        ps = fmaf(h[j], as1[c0 + j], ps);
        pd = fmaf(h[j], ad1[c0 + j], pd);
    }
#pragma unroll
    for (int s = 4; s >= 1; s >>= 1) {
        ps += __shfl_down_sync(0xffffffffu, ps, s, 8);
        pd += __shfl_down_sync(0xffffffffu, pd, s, 8);
    }
    if ((lane & 7) == 0) {
        g_al1[n * 8 + head]     = ps;
        g_al1[n * 8 + 4 + head] = pd;
    }
}

// ---------------- CSR scan (decoupled lookback) + den1 zeroing ----------------
__global__ void __launch_bounds__(256) k_scan(int N, int NB) {
    int b = blockIdx.x, t = threadIdx.x;
    int i = b * 256 + t;
    int c = (i < N) ? g_cnt[i] : 0;
    // zero den1 here (runs before scatter, after hist)
    if (i < N) *(float4*)(g_den1 + (size_t)i * 4) = make_float4(0.f, 0.f, 0.f, 0.f);
    int v = c;
#pragma unroll
    for (int s = 1; s < 32; s <<= 1) {
        int u = __shfl_up_sync(0xffffffffu, v, s);
        if ((t & 31) >= s) v += u;
    }
    __shared__ int wsum[8];
    __shared__ int s_agg, s_base;
    if ((t & 31) == 31) wsum[t >> 5] = v;
    __syncthreads();
    if (t == 0) {
        int run = 0;
#pragma unroll
        for (int w = 0; w < 8; w++) { int x = wsum[w]; wsum[w] = run; run += x; }
        s_agg = run;
        atomicExch(&g_pub[b], run + 1);
    }
    __syncthreads();
    int loc = v - c + wsum[t >> 5];

    int pred = 0;
    if (t < b) {
        int x;
        while ((x = atomicAdd(&g_pub[t], 0)) == 0) {}
        pred = x - 1;
    }
#pragma unroll
    for (int s = 16; s >= 1; s >>= 1) pred += __shfl_down_sync(0xffffffffu, pred, s);
    __shared__ int psum[8];
    if ((t & 31) == 0) psum[t >> 5] = pred;
    __syncthreads();
    if (t == 0) {
        int base = 0;
#pragma unroll
        for (int w = 0; w < 8; w++) base += psum[w];
        s_base = base;
    }
    __syncthreads();
    int o = loc + s_base;
    if (i < N) { g_offs[i] = o; g_cursor[i] = o; }
    if (b == NB - 1 && t == 0) g_offs[N] = s_base + s_agg;
}

// ---------------- CSR scatter + weights + den (2 edges/thread for MLP) ----------------
__global__ void __launch_bounds__(256) k_scatter(int E, int N) {
    int total = E + N;
    int base = blockIdx.x * 512 + threadIdx.x;

    int e0 = base, e1 = base + 256;
    bool v0 = e0 < total, v1 = e1 < total;
    int s0 = 0, d0 = 0, s1 = 0, d1 = 0;
    if (v0) {
        if (e0 < E) { s0 = g_src32[e0]; d0 = g_dst32[e0]; }
        else        { s0 = d0 = e0 - E; }
    }
    if (v1) {
        if (e1 < E) { s1 = g_src32[e1]; d1 = g_dst32[e1]; }
        else        { s1 = d1 = e1 - E; }
    }
    if (v0) place_edge(s0, d0);
    if (v1) place_edge(s1, d1);
}

// ---------------- FUSED HEAVY: layer-1 agg (fp8, half2, int4 index loads) + node2 ----------------
__global__ void __launch_bounds__(256) k_agg1n2(
    const float* __restrict__ b1, const float* __restrict__ W2,
    const float* __restrict__ a_src2, const float* __restrict__ a_dst2, int N)
{
    __shared__ float W2s[F1 * OUTCH];   // 6 KB
    __shared__ float b1s[F1];
    __shared__ float as2[OUTCH], ad2[OUTCH];
    int tid = threadIdx.x;
    for (int i = tid; i < F1 * OUTCH; i += 256) W2s[i] = W2[i];
    b1s[tid] = b1[tid];
    if (tid < OUTCH) { as2[tid] = a_src2[tid]; ad2[tid] = a_dst2[tid]; }
    __syncthreads();

    int n = (blockIdx.x * blockDim.x + tid) >> 5;
    if (n >= N) return;
    int lane = tid & 31;
    int c0 = lane * 8;
    int head = lane >> 3;
    int start = g_offs[n], end = g_offs[n + 1];

    __half2 zh = __float2half2_rn(0.f);
    __half2 a0[4] = {zh, zh, zh, zh};
    __half2 a1[4] = {zh, zh, zh, zh};

    int j = start;
    // peel to 16B alignment of g_sorted + j
    for (; j < end && (j & 3); j++) {
        int s0 = g_sorted[j];
        unsigned short w0 = g_wqh[(size_t)j * 4 + head];
        uint2 r0 = *(const uint2*)(g_h1q + (size_t)s0 * F1 + c0);
        acc_row_h2(a0, r0, __half2half2(__ushort_as_half(w0)));
    }
    for (; j + 4 <= end; j += 4) {
        int4 ss = *(const int4*)(g_sorted + j);      // 1 wavefront (uniform)
        unsigned short w0 = g_wqh[(size_t)(j    ) * 4 + head];
        unsigned short w1 = g_wqh[(size_t)(j + 1) * 4 + head];
        unsigned short w2 = g_wqh[(size_t)(j + 2) * 4 + head];
        unsigned short w3 = g_wqh[(size_t)(j + 3) * 4 + head];
        uint2 r0 = *(const uint2*)(g_h1q + (size_t)ss.x * F1 + c0);
        uint2 r1 = *(const uint2*)(g_h1q + (size_t)ss.y * F1 + c0);
        uint2 r2 = *(const uint2*)(g_h1q + (size_t)ss.z * F1 + c0);
        uint2 r3 = *(const uint2*)(g_h1q + (size_t)ss.w * F1 + c0);
        acc_row_h2(a0, r0, __half2half2(__ushort_as_half(w0)));
        acc_row_h2(a1, r1, __half2half2(__ushort_as_half(w1)));
        acc_row_h2(a0, r2, __half2half2(__ushort_as_half(w2)));
        acc_row_h2(a1, r3, __half2half2(__ushort_as_half(w3)));
    }
    for (; j < end; j++) {
        int s0 = g_sorted[j];
        unsigned short w0 = g_wqh[(size_t)j * 4 + head];
        uint2 r0 = *(const uint2*)(g_h1q + (size_t)s0 * F1 + c0);
        acc_row_h2(a0, r0, __half2half2(__ushort_as_half(w0)));
    }

    // flush half2 accumulators to fp32
    float acc[8];
#pragma unroll
    for (int k = 0; k < 4; k++) {
        float2 t0 = __half22float2(a0[k]);
        float2 t1 = __half22float2(a1[k]);
        acc[2 * k]     = t0.x + t1.x;
        acc[2 * k + 1] = t0.y + t1.y;
    }

    float inv = 1.f / g_den1[(size_t)n * 4 + head];

    float z[OUTCH];
#pragma unroll
    for (int jj = 0; jj < OUTCH; jj++) z[jj] = 0.f;
#pragma unroll
    for (int k = 0; k < 8; k++) {
        float t = fmaf(acc[k], inv, b1s[c0 + k]);
        t = t > 0.f ? t : expm1f(t);      // elu
#pragma unroll
        for (int jj = 0; jj < OUTCH; jj++) z[jj] = fmaf(t, W2s[(c0 + k) * OUTCH + jj], z[jj]);
    }
#pragma unroll
    for (int jj = 0; jj < OUTCH; jj++)
#pragma unroll
        for (int s = 16; s >= 1; s >>= 1)
            z[jj] += __shfl_down_sync(0xffffffffu, z[jj], s);

    if (lane == 0) {
        float as = 0.f, ad = 0.f;
#pragma unroll
        for (int jj = 0; jj < OUTCH; jj++) { as = fmaf(z[jj], as2[jj], as); ad = fmaf(z[jj], ad2[jj], ad); }
        float4* o = (float4*)(g_h2 + (size_t)n * 8);
        o[0] = make_float4(z[0], z[1], z[2], z[3]);
        o[1] = make_float4(z[4], z[5], as, ad);   // [h4, h5, al_src2, al_dst2]
    }
}

// ---------------- layer-2 aggregation + log_softmax (8 lanes per dst) ----------------
__global__ void __launch_bounds__(256) k_agg2(
    const float* __restrict__ b2, float* __restrict__ out, int N)
{
    int n = (blockIdx.x * blockDim.x + threadIdx.x) >> 3;
    if (n >= N) return;
    int sl = threadIdx.x & 7;
    int start = g_offs[n], end = g_offs[n + 1];

    float ald = g_h2[(size_t)n * 8 + 7];
    float acc[OUTCH] = {0.f, 0.f, 0.f, 0.f, 0.f, 0.f};
    float den = 0.f;

    int idx = start + sl;
    for (; idx + 8 < end; idx += 16) {
        int srcA = g_sorted[idx];
        int srcB = g_sorted[idx + 8];
        const float4* hA = (const float4*)(g_h2 + (size_t)srcA * 8);
        const float4* hB = (const float4*)(g_h2 + (size_t)srcB * 8);
        float4 aA = hA[0], bA = hA[1];
        float4 aB = hB[0], bB = hB[1];
        float wA = __expf(lrelu(bA.z + ald));
        float wB = __expf(lrelu(bB.z + ald));
        acc[0] = fmaf(wA, aA.x, acc[0]); acc[1] = fmaf(wA, aA.y, acc[1]);
        acc[2] = fmaf(wA, aA.z, acc[2]); acc[3] = fmaf(wA, aA.w, acc[3]);
        acc[4] = fmaf(wA, bA.x, acc[4]); acc[5] = fmaf(wA, bA.y, acc[5]);
        den += wA;
        acc[0] = fmaf(wB, aB.x, acc[0]); acc[1] = fmaf(wB, aB.y, acc[1]);
        acc[2] = fmaf(wB, aB.z, acc[2]); acc[3] = fmaf(wB, aB.w, acc[3]);
        acc[4] = fmaf(wB, bB.x, acc[4]); acc[5] = fmaf(wB, bB.y, acc[5]);
        den += wB;
    }
    if (idx < end) {
        int src = g_sorted[idx];
        const float4* hp = (const float4*)(g_h2 + (size_t)src * 8);
        float4 a = hp[0], b = hp[1];
        float w = __expf(lrelu(b.z + ald));
        acc[0] = fmaf(w, a.x, acc[0]); acc[1] = fmaf(w, a.y, acc[1]);
        acc[2] = fmaf(w, a.z, acc[2]); acc[3] = fmaf(w, a.w, acc[3]);
        acc[4] = fmaf(w, b.x, acc[4]); acc[5] = fmaf(w, b.y, acc[5]);
        den += w;
    }
#pragma unroll
    for (int s = 4; s >= 1; s >>= 1) {
#pragma unroll
        for (int jj = 0; jj < OUTCH; jj++) acc[jj] += __shfl_down_sync(0xffffffffu, acc[jj], s, 8);
        den += __shfl_down_sync(0xffffffffu, den, s, 8);
    }
    if (sl == 0) {
        float inv = 1.f / den;
        float y[OUTCH], mx = -1e30f;
#pragma unroll
        for (int jj = 0; jj < OUTCH; jj++) {
            y[jj] = fmaf(acc[jj], inv, b2[jj]);
            mx = fmaxf(mx, y[jj]);
        }
        float s = 0.f;
#pragma unroll
        for (int jj = 0; jj < OUTCH; jj++) s += expf(y[jj] - mx);
        float l = mx + logf(s);
#pragma unroll
        for (int jj = 0; jj < OUTCH; jj++) out[(size_t)n * OUTCH + jj] = y[jj] - l;
    }
}

extern "C" void kernel_launch(void* const* d_in, const int* in_sizes, int n_in,
                              void* d_out, int out_size)
{
    const float* x      = (const float*)d_in[0];
    const void*  ei     = d_in[1];
    const float* W1     = (const float*)d_in[2];
    const float* a_src1 = (const float*)d_in[3];
    const float* a_dst1 = (const float*)d_in[4];
    const float* b1     = (const float*)d_in[5];
    const float* W2     = (const float*)d_in[6];
    const float* a_src2 = (const float*)d_in[7];
    const float* a_dst2 = (const float*)d_in[8];
    const float* b2     = (const float*)d_in[9];
    float*       out    = (float*)d_out;

    int N    = in_sizes[0] / INCH;
    int E    = in_sizes[1] / 2;
    int TE   = E + N;
    int NB   = (N + 255) / 256;
    int NBn  = (N + 7) / 8;
    int NBe2 = (TE + 511) / 512;

    void* p_cnt;
    cudaGetSymbolAddress(&p_cnt, g_cnt);
    cudaMemsetAsync(p_cnt, 0, (size_t)N * sizeof(int), 0);

    k_node1_hist<<<NBn + NBe2, 256>>>(x, W1, a_src1, a_dst1, ei, E, N, NBn);
    k_scan<<<NB, 256>>>(N, NB);
    k_scatter<<<NBe2, 256>>>(E, N);
    k_agg1n2<<<(N * 32 + 255) / 256, 256>>>(b1, W2, a_src2, a_dst2, N);
    k_agg2<<<(N * 8 + 255) / 256, 256>>>(b2, out, N);
}